// round 16
// baseline (speedup 1.0000x reference)
#include <cuda_runtime.h>
#include <cuda_fp16.h>
#include <cstdint>

typedef __half fp16;

#define Bx 4
#define Sx 2048
#define Hx 1024
#define Mx 8192            // B*S
#define CH 32              // scan chunk length
#define NCH 64             // S / CH
#define NPERS 304          // persistent grid: 2 CTAs/SM x 152 SMs

// ---------------- device scratch ----------------
__device__ __align__(256) fp16  g_Xh[Mx * Hx];
__device__ __align__(256) fp16  g_Wh[3 * Hx * Hx];    // [Wi, Wf, Wg] fp16
__device__ __align__(256) fp16  g_Woh[Hx * Hx];
__device__ __align__(256) fp16  g_Yi[Mx * Hx];        // silu(i_raw)   (fp16)
__device__ __align__(256) fp16  g_Yf[Mx * Hx];        // sigmoid(f_raw)(fp16)
__device__ __align__(256) fp16  g_Yg[Mx * Hx];        // g raw (fp16)
__device__ __align__(256) __half2 g_PH[Mx * Hx];      // {cumprod(f), h_local}
__device__ __align__(256) fp16  g_GH[Mx * Hx];
__device__ float g_P[Bx * Hx * NCH];                  // [b][h][c] channel-major
__device__ float g_E[Bx * Hx * NCH];                  // [b][h][c]

// ---------------- PTX helpers ----------------
__device__ __forceinline__ uint32_t smem_u32(const void* p) {
    uint32_t a;
    asm("{ .reg .u64 t; cvta.to.shared.u64 t, %1; cvt.u32.u64 %0, t; }" : "=r"(a) : "l"(p));
    return a;
}

__device__ __forceinline__ uint32_t h2_bits(__half2 h) {
    uint32_t u;
    *(__half2*)&u = h;
    return u;
}

__device__ __forceinline__ void ldsm_x4(uint32_t& r0, uint32_t& r1, uint32_t& r2,
                                        uint32_t& r3, uint32_t addr) {
    asm volatile("ldmatrix.sync.aligned.m8n8.x4.shared.b16 {%0,%1,%2,%3}, [%4];"
                 : "=r"(r0), "=r"(r1), "=r"(r2), "=r"(r3) : "r"(addr));
}

__device__ __forceinline__ void mma_fp16(float* c, const uint32_t* a, const uint32_t* b) {
    asm volatile(
        "mma.sync.aligned.m16n8k16.row.col.f32.f16.f16.f32 "
        "{%0,%1,%2,%3}, {%4,%5,%6,%7}, {%8,%9}, {%0,%1,%2,%3};"
        : "+f"(c[0]), "+f"(c[1]), "+f"(c[2]), "+f"(c[3])
        : "r"(a[0]), "r"(a[1]), "r"(a[2]), "r"(a[3]), "r"(b[0]), "r"(b[1]));
}

// epilogue transforms: mode 0 = silu, 1 = sigmoid, 2 = identity
__device__ __forceinline__ float ep_xform(float v, int mode) {
    if (mode == 0) return v / (1.f + __expf(-v));          // silu
    if (mode == 1) return 1.f / (1.f + __expf(-v));        // sigmoid
    return v;
}

// ---------------- persistent GEMM (R13 config — best passing) ---------------
// CTA tile 128x128, K-chunk 64, 3-slot cp.async pipeline, continuous global
// iteration counter, race-free cross-stage fragment prefetch.
// 8 warps (2x4), warp tile 64x32, 256 threads, 2 CTAs/SM.
#define STAGE_BYTES 32768u          // 2 tiles x (128 x 64 fp16)
#define GEMM_SMEM   (1024 + 3 * 32768)
#define GTHREADS 256

__device__ __forceinline__ void load_tile(uint32_t tb, const fp16* __restrict__ src,
                                          int row0, int k0, int tid) {
    const char* gbase = (const char*)(src + (size_t)row0 * Hx + k0);
#pragma unroll
    for (int i = 0; i < 4; i++) {
        int gid = tid + i * 256;        // 1024 granules of 16B
        int row = gid >> 3;
        int g   = gid & 7;
        const char* gp = gbase + (size_t)row * (Hx * 2) + g * 16;
        uint32_t sp = tb + (uint32_t)(row * 128) + (uint32_t)((g ^ (row & 7)) << 4);
        asm volatile("cp.async.cg.shared.global [%0], [%1], 16;"
                     :: "r"(sp), "l"(gp) : "memory");
    }
}

// tile index -> coords: z = t/512, m0 = ((t%512)/8)*128, n0 = (t%8)*128
struct TileC { int m0, n0, z; };
__device__ __forceinline__ TileC tile_coords(int t) {
    TileC c;
    c.z  = t >> 9;
    int r = t & 511;
    c.m0 = (r >> 3) << 7;
    c.n0 = (r & 7) << 7;
    return c;
}

template <typename OutT, bool ACT>
__global__ void __launch_bounds__(GTHREADS, 2) k_gemm_p(
    const fp16* __restrict__ Ah,
    const fp16* __restrict__ Bh_,
    OutT* __restrict__ C0, OutT* __restrict__ C1, OutT* __restrict__ C2,
    int zstride, int ntiles)
{
    extern __shared__ char smem_raw[];
    uint32_t sb     = smem_u32(smem_raw);
    uint32_t stage0 = (sb + 1023u) & ~1023u;

    const int tid = threadIdx.x;
    const int wid = tid >> 5;
    const int lid = tid & 31;
    const int wr  = wid >> 2;       // 0-1  -> m offset wr*64
    const int wc  = wid & 3;        // 0-3  -> n offset wc*32
    const int bid = blockIdx.x;
    if (bid >= ntiles) return;
    const int T = (ntiles - 1 - bid) / NPERS + 1;   // my tile count

    const int aRow = lid & 15;
    const int aCg  = lid >> 4;
    const int bRow = (lid & 7) | ((lid & 16) >> 1);
    const int bCg  = (lid >> 3) & 1;
    const uint32_t aSwz = (uint32_t)(aRow & 7);
    const uint32_t bSwz = (uint32_t)(bRow & 7);
    uint32_t aOff[4], bOff[2];
#pragma unroll
    for (int mt = 0; mt < 4; mt++) aOff[mt] = (uint32_t)((wr * 64 + mt * 16 + aRow) * 128);
#pragma unroll
    for (int nt = 0; nt < 2; nt++) bOff[nt] = (uint32_t)((wc * 32 + nt * 16 + bRow) * 128);

    uint32_t ah[2][4][4], bhf[2][2][4];

#define LOAD_FRAGS(buf, sbase, ks_) do {                                        \
    uint32_t soA = (uint32_t)(((2 * (ks_) + aCg) ^ aSwz) << 4);                 \
    uint32_t soB = (uint32_t)(((2 * (ks_) + bCg) ^ bSwz) << 4);                 \
    _Pragma("unroll")                                                           \
    for (int mt = 0; mt < 4; mt++) {                                            \
        ldsm_x4(ah[buf][mt][0], ah[buf][mt][1], ah[buf][mt][2], ah[buf][mt][3], \
                (sbase) + aOff[mt] + soA);                                      \
    }                                                                           \
    _Pragma("unroll")                                                           \
    for (int nt = 0; nt < 2; nt++) {                                            \
        ldsm_x4(bhf[buf][nt][0], bhf[buf][nt][1], bhf[buf][nt][2],              \
                bhf[buf][nt][3], (sbase) + 16384u + bOff[nt] + soB);            \
    }                                                                           \
} while (0)

#define COMPUTE(buf) do {                                                       \
    _Pragma("unroll")                                                           \
    for (int mt = 0; mt < 4; mt++)                                              \
        _Pragma("unroll")                                                       \
        for (int nt = 0; nt < 4; nt++) {                                        \
            const uint32_t* bh2 = &bhf[buf][nt >> 1][(nt & 1) * 2];             \
            mma_fp16(acc[mt][nt], ah[buf][mt], bh2);                            \
        }                                                                       \
} while (0)

    // prologue: global iters 0,1 = tile0 k=0,1
    TileC cur = tile_coords(bid);
    const fp16* curB = Bh_ + (size_t)cur.z * zstride;
#pragma unroll
    for (int s = 0; s < 2; s++) {
        uint32_t st = stage0 + s * STAGE_BYTES;
        load_tile(st,          Ah,   cur.m0, s * 64, tid);
        load_tile(st + 16384u, curB, cur.n0, s * 64, tid);
        asm volatile("cp.async.commit_group;" ::: "memory");
    }

    int it = 0;                // continuous global iteration
    bool first = true;
    for (int j = 0; j < T; j++) {
        TileC nxt;
        const fp16* nxtB = nullptr;
        bool have_nxt = (j + 1 < T);
        if (have_nxt) {
            nxt  = tile_coords(bid + (j + 1) * NPERS);
            nxtB = Bh_ + (size_t)nxt.z * zstride;
        }

        float acc[4][4][4];
#pragma unroll
        for (int a = 0; a < 4; a++)
#pragma unroll
            for (int b = 0; b < 4; b++)
#pragma unroll
                for (int c = 0; c < 4; c++) acc[a][b][c] = 0.f;

        for (int k = 0; k < 16; k++, it++) {
            uint32_t sbase = stage0 + (uint32_t)(it % 3) * STAGE_BYTES;
            bool last_it = (j == T - 1) && (k == 15);

            // ALL outstanding copies complete for every thread BEFORE the
            // barrier -> any smem read below is race-free.
            asm volatile("cp.async.wait_group 0;" ::: "memory");
            __syncthreads();   // also: slot (it-1)%3 free for reuse

            // issue loads for global iter it+2 into slot (it+2)%3 == (it-1)%3
            uint32_t lbase = stage0 + (uint32_t)((it + 2) % 3) * STAGE_BYTES;
            if (k < 14) {
                load_tile(lbase,          Ah,   cur.m0, (k + 2) * 64, tid);
                load_tile(lbase + 16384u, curB, cur.n0, (k + 2) * 64, tid);
                asm volatile("cp.async.commit_group;" ::: "memory");
            } else if (have_nxt) {
                load_tile(lbase,          Ah,   nxt.m0, (k - 14) * 64, tid);
                load_tile(lbase + 16384u, nxtB, nxt.n0, (k - 14) * 64, tid);
                asm volatile("cp.async.commit_group;" ::: "memory");
            }

            if (first) { LOAD_FRAGS(0, sbase, 0); first = false; }

#pragma unroll
            for (int ks = 0; ks < 4; ks++) {
                int cb = ks & 1;
                if (ks < 3) {
                    LOAD_FRAGS((cb ^ 1), sbase, (ks + 1));
                } else if (!last_it) {
                    // prefetch next stage's ks=0 frags (slot (it+1)%3 —
                    // complete and block-visible since before the barrier)
                    uint32_t nbase = stage0 + (uint32_t)((it + 1) % 3) * STAGE_BYTES;
                    LOAD_FRAGS((cb ^ 1), nbase, 0);
                }
                COMPUTE(cb);
            }
        }

        // epilogue (registers -> gmem only; overlaps in-flight cp.async)
        OutT* C = (cur.z == 0) ? C0 : ((cur.z == 1) ? C1 : C2);
        const int mode = ACT ? cur.z : 2;
        const int g4 = lid >> 2;
        const int t4 = lid & 3;
#pragma unroll
        for (int mt = 0; mt < 4; mt++) {
            int row = cur.m0 + wr * 64 + mt * 16 + g4;
#pragma unroll
            for (int nt = 0; nt < 4; nt++) {
                int col = cur.n0 + wc * 32 + nt * 8 + t4 * 2;
                float v0 = ep_xform(acc[mt][nt][0], mode);
                float v1 = ep_xform(acc[mt][nt][1], mode);
                float v2 = ep_xform(acc[mt][nt][2], mode);
                float v3 = ep_xform(acc[mt][nt][3], mode);
                if constexpr (sizeof(OutT) == 2) {
                    *(__half2*)((fp16*)C + (size_t)row * Hx + col)       = __floats2half2_rn(v0, v1);
                    *(__half2*)((fp16*)C + (size_t)(row + 8) * Hx + col) = __floats2half2_rn(v2, v3);
                } else {
                    *(float2*)((float*)C + (size_t)row * Hx + col)       = make_float2(v0, v1);
                    *(float2*)((float*)C + (size_t)(row + 8) * Hx + col) = make_float2(v2, v3);
                }
            }
        }

        cur = nxt;
        curB = nxtB;
    }
}

// ---------------- fused fp32 -> fp16 conversions, x4 vectorized ------------
#define NEc (Mx * Hx)
#define NWc (Hx * Hx)
__global__ void k_cvt_all(const float* __restrict__ x,  const float* __restrict__ Wi,
                          const float* __restrict__ Wf, const float* __restrict__ Wg,
                          const float* __restrict__ Wo) {
    int i = blockIdx.x * blockDim.x + threadIdx.x;      // over (NE + 4NW)/4
    const float* s;
    fp16* d;
    int o;
    if (i < NEc / 4) {
        s = x; d = g_Xh; o = i;
    } else {
        int j = i - NEc / 4;
        int y = j >> 18;                 // j / (NWc/4)
        o = j & (NWc / 4 - 1);
        s = (y == 0) ? Wi : (y == 1) ? Wf : (y == 2) ? Wg : Wo;
        d = (y < 3) ? (g_Wh + (size_t)y * NWc) : g_Woh;
    }
    float4 v = ((const float4*)s)[o];
    __half2 h0 = __floats2half2_rn(v.x, v.y);
    __half2 h1 = __floats2half2_rn(v.z, v.w);
    ((uint2*)d)[o] = make_uint2(h2_bits(h0), h2_bits(h1));
}

// pass 1: chunk-local scan, 2 h-channels per thread (half2 path).
// Writes PH (time-major) and chunk summaries P/E in CHANNEL-MAJOR layout
// [b][h][c] so the lookback in k_scan3 reads contiguous runs.
__global__ void k_scan1() {
    int tid = blockIdx.x * blockDim.x + threadIdx.x;   // B*NCH*H/2 = 131072
    int h2 = tid & 511;          // h-pair, 0..511
    int bc = tid >> 9;           // b*NCH + c
    int b  = bc >> 6;
    int c  = bc & (NCH - 1);
    size_t base2 = ((size_t)(b * Sx + c * CH)) * (Hx / 2) + h2;
    const __half2* Yf2 = (const __half2*)g_Yf;
    const __half2* Yi2 = (const __half2*)g_Yi;
    float p0 = 1.f, hl0 = 0.f, p1 = 1.f, hl1 = 0.f;
#pragma unroll 4
    for (int t = 0; t < CH; t++) {
        size_t idx = base2 + (size_t)t * (Hx / 2);
        float2 f2 = __half22float2(Yf2[idx]);
        float2 i2 = __half22float2(Yi2[idx]);
        hl0 = f2.x * hl0 + i2.x * (1.f - f2.x);
        p0  = p0 * f2.x;
        hl1 = f2.y * hl1 + i2.y * (1.f - f2.y);
        p1  = p1 * f2.y;
        __half2 ph0 = __floats2half2_rn(p0, hl0);
        __half2 ph1 = __floats2half2_rn(p1, hl1);
        ((uint2*)g_PH)[idx] = make_uint2(h2_bits(ph0), h2_bits(ph1));
    }
    // channel-major summaries: [b][h][c]
    int s0 = ((b * Hx + 2 * h2) * NCH) + c;
    g_P[s0]       = p0;
    g_E[s0]       = hl0;
    g_P[s0 + NCH] = p1;
    g_E[s0 + NCH] = hl1;
}

// pass 2 (fused lookback + apply): one block per (b, chunk, h-group).
// Grid = Bx * NCH * 2 (two 256-thread h-groups cover the 512 half2 pairs).
// Each thread serially composes its channel's c preceding affine summaries
// (contiguous [b][h][0..c-1] runs, L2-resident) to get the carry, then
// applies the 32-step chunk: h = h_local + cumprod*carry; gh = g*h.
__global__ void k_scan3() {
    int bid = blockIdx.x;            // Bx * NCH * 2 = 512 blocks
    int hg  = bid & 1;               // h-group: 256 half2 pairs each
    int c   = (bid >> 1) & (NCH - 1);
    int b   = bid >> 7;
    int h2  = hg * 256 + threadIdx.x;    // half2 index 0..511
    int h0  = 2 * h2;

    // lookback: carry = composition of chunks 0..c-1 for channels h0, h0+1
    float carry0 = 0.f, carry1 = 0.f;
    const float* P0 = g_P + ((size_t)(b * Hx + h0) * NCH);
    const float* E0 = g_E + ((size_t)(b * Hx + h0) * NCH);
#pragma unroll 4
    for (int cc = 0; cc < c; cc++) {
        float pa = P0[cc],       ea = E0[cc];
        float pb = P0[NCH + cc], eb = E0[NCH + cc];
        carry0 = pa * carry0 + ea;
        carry1 = pb * carry1 + eb;
    }

    // apply chunk c
    const __half2* Yg2 = (const __half2*)g_Yg;
    __half2* GH2 = (__half2*)g_GH;
    size_t base2 = ((size_t)(b * Sx + c * CH)) * (Hx / 2) + h2;
#pragma unroll 4
    for (int t = 0; t < CH; t++) {
        size_t idx = base2 + (size_t)t * (Hx / 2);
        uint2 phu = ((const uint2*)g_PH)[idx];
        __half2 ph0 = *(__half2*)&phu.x;
        __half2 ph1 = *(__half2*)&phu.y;
        float hv0 = __high2float(ph0) + __low2float(ph0) * carry0;
        float hv1 = __high2float(ph1) + __low2float(ph1) * carry1;
        float2 g2 = __half22float2(Yg2[idx]);
        GH2[idx] = __floats2half2_rn(g2.x * hv0, g2.y * hv1);
    }
}

// ---------------- launch ----------------
extern "C" void kernel_launch(void* const* d_in, const int* in_sizes, int n_in,
                              void* d_out, int out_size) {
    const float* x  = (const float*)d_in[0];
    const float* Wi = (const float*)d_in[1];
    const float* Wf = (const float*)d_in[2];
    const float* Wg = (const float*)d_in[3];
    const float* Wo = (const float*)d_in[4];
    float* out = (float*)d_out;

    cudaFuncSetAttribute((const void*)k_gemm_p<fp16, true>,
                         cudaFuncAttributeMaxDynamicSharedMemorySize, GEMM_SMEM);
    cudaFuncSetAttribute((const void*)k_gemm_p<float, false>,
                         cudaFuncAttributeMaxDynamicSharedMemorySize, GEMM_SMEM);

    fp16 *Xh, *Wh, *Woh, *GH, *Yi, *Yf, *Yg;
    cudaGetSymbolAddress((void**)&Xh,  g_Xh);
    cudaGetSymbolAddress((void**)&Wh,  g_Wh);
    cudaGetSymbolAddress((void**)&Woh, g_Woh);
    cudaGetSymbolAddress((void**)&GH,  g_GH);
    cudaGetSymbolAddress((void**)&Yi,  g_Yi);
    cudaGetSymbolAddress((void**)&Yf,  g_Yf);
    cudaGetSymbolAddress((void**)&Yg,  g_Yg);

    const int NE = Mx * Hx;     // 8388608
    const int NW = Hx * Hx;     // 1048576

    // conversions (x4 vectorized)
    k_cvt_all<<<(NE / 4 + NW) / 256, 256>>>(x, Wi, Wf, Wg, Wo);

    // GEMM1 (persistent): Yi = silu(x@Wi^T), Yf = sigmoid(x@Wf^T), Yg = x@Wg^T
    k_gemm_p<fp16, true><<<NPERS, GTHREADS, GEMM_SMEM>>>(Xh, Wh, Yi, Yf, Yg, NW, 1536);

    // chunked linear recurrence (2 kernels: local scan, lookback+apply)
    k_scan1<<<(Bx * NCH * Hx / 2) / 256, 256>>>();
    k_scan3<<<Bx * NCH * 2, 256>>>();

    // GEMM2 (persistent): out = (g*h) @ Wo^T
    k_gemm_p<float, false><<<NPERS, GTHREADS, GEMM_SMEM>>>(GH, Woh, out, out, out, 0, 512);
}

// round 17
// speedup vs baseline: 1.4515x; 1.4515x over previous
#include <cuda_runtime.h>
#include <cuda_fp16.h>
#include <cstdint>

typedef __half fp16;

#define Bx 4
#define Sx 2048
#define Hx 1024
#define Mx 8192            // B*S
#define CH 32              // scan chunk length
#define NCH 64             // S / CH
#define NPERS 304          // persistent grid: 2 CTAs/SM x 152 SMs

// ---------------- device scratch ----------------
__device__ __align__(256) fp16  g_Xh[Mx * Hx];
__device__ __align__(256) fp16  g_Wh[3 * Hx * Hx];    // [Wi, Wf, Wg] fp16
__device__ __align__(256) fp16  g_Woh[Hx * Hx];
__device__ __align__(256) fp16  g_Yi[Mx * Hx];        // silu(i_raw)   (fp16)
__device__ __align__(256) fp16  g_Yf[Mx * Hx];        // sigmoid(f_raw)(fp16)
__device__ __align__(256) fp16  g_Yg[Mx * Hx];        // g raw (fp16)
__device__ __align__(256) __half2 g_PH[Mx * Hx];      // {cumprod(f), h_local}
__device__ __align__(256) fp16  g_GH[Mx * Hx];
__device__ float g_P[Bx * NCH * Hx];                  // [b][c][h] time-major
__device__ float g_E[Bx * NCH * Hx];
__device__ float g_Cr[Bx * NCH * Hx];

// ---------------- PTX helpers ----------------
__device__ __forceinline__ uint32_t smem_u32(const void* p) {
    uint32_t a;
    asm("{ .reg .u64 t; cvta.to.shared.u64 t, %1; cvt.u32.u64 %0, t; }" : "=r"(a) : "l"(p));
    return a;
}

__device__ __forceinline__ uint32_t h2_bits(__half2 h) {
    uint32_t u;
    *(__half2*)&u = h;
    return u;
}

__device__ __forceinline__ void ldsm_x4(uint32_t& r0, uint32_t& r1, uint32_t& r2,
                                        uint32_t& r3, uint32_t addr) {
    asm volatile("ldmatrix.sync.aligned.m8n8.x4.shared.b16 {%0,%1,%2,%3}, [%4];"
                 : "=r"(r0), "=r"(r1), "=r"(r2), "=r"(r3) : "r"(addr));
}

__device__ __forceinline__ void mma_fp16(float* c, const uint32_t* a, const uint32_t* b) {
    asm volatile(
        "mma.sync.aligned.m16n8k16.row.col.f32.f16.f16.f32 "
        "{%0,%1,%2,%3}, {%4,%5,%6,%7}, {%8,%9}, {%0,%1,%2,%3};"
        : "+f"(c[0]), "+f"(c[1]), "+f"(c[2]), "+f"(c[3])
        : "r"(a[0]), "r"(a[1]), "r"(a[2]), "r"(a[3]), "r"(b[0]), "r"(b[1]));
}

// epilogue transforms: mode 0 = silu, 1 = sigmoid, 2 = identity
__device__ __forceinline__ float ep_xform(float v, int mode) {
    if (mode == 0) return v / (1.f + __expf(-v));          // silu
    if (mode == 1) return 1.f / (1.f + __expf(-v));        // sigmoid
    return v;
}

// ---------------- persistent GEMM (R13 config — best passing) ---------------
// CTA tile 128x128, K-chunk 64, 3-slot cp.async pipeline, continuous global
// iteration counter, race-free cross-stage fragment prefetch.
// 8 warps (2x4), warp tile 64x32, 256 threads, 2 CTAs/SM.
#define STAGE_BYTES 32768u          // 2 tiles x (128 x 64 fp16)
#define GEMM_SMEM   (1024 + 3 * 32768)
#define GTHREADS 256

__device__ __forceinline__ void load_tile(uint32_t tb, const fp16* __restrict__ src,
                                          int row0, int k0, int tid) {
    const char* gbase = (const char*)(src + (size_t)row0 * Hx + k0);
#pragma unroll
    for (int i = 0; i < 4; i++) {
        int gid = tid + i * 256;        // 1024 granules of 16B
        int row = gid >> 3;
        int g   = gid & 7;
        const char* gp = gbase + (size_t)row * (Hx * 2) + g * 16;
        uint32_t sp = tb + (uint32_t)(row * 128) + (uint32_t)((g ^ (row & 7)) << 4);
        asm volatile("cp.async.cg.shared.global [%0], [%1], 16;"
                     :: "r"(sp), "l"(gp) : "memory");
    }
}

// tile index -> coords: z = t/512, m0 = ((t%512)/8)*128, n0 = (t%8)*128
struct TileC { int m0, n0, z; };
__device__ __forceinline__ TileC tile_coords(int t) {
    TileC c;
    c.z  = t >> 9;
    int r = t & 511;
    c.m0 = (r >> 3) << 7;
    c.n0 = (r & 7) << 7;
    return c;
}

template <typename OutT, bool ACT>
__global__ void __launch_bounds__(GTHREADS, 2) k_gemm_p(
    const fp16* __restrict__ Ah,
    const fp16* __restrict__ Bh_,
    OutT* __restrict__ C0, OutT* __restrict__ C1, OutT* __restrict__ C2,
    int zstride, int ntiles)
{
    extern __shared__ char smem_raw[];
    uint32_t sb     = smem_u32(smem_raw);
    uint32_t stage0 = (sb + 1023u) & ~1023u;

    const int tid = threadIdx.x;
    const int wid = tid >> 5;
    const int lid = tid & 31;
    const int wr  = wid >> 2;       // 0-1  -> m offset wr*64
    const int wc  = wid & 3;        // 0-3  -> n offset wc*32
    const int bid = blockIdx.x;
    if (bid >= ntiles) return;
    const int T = (ntiles - 1 - bid) / NPERS + 1;   // my tile count

    const int aRow = lid & 15;
    const int aCg  = lid >> 4;
    const int bRow = (lid & 7) | ((lid & 16) >> 1);
    const int bCg  = (lid >> 3) & 1;
    const uint32_t aSwz = (uint32_t)(aRow & 7);
    const uint32_t bSwz = (uint32_t)(bRow & 7);
    uint32_t aOff[4], bOff[2];
#pragma unroll
    for (int mt = 0; mt < 4; mt++) aOff[mt] = (uint32_t)((wr * 64 + mt * 16 + aRow) * 128);
#pragma unroll
    for (int nt = 0; nt < 2; nt++) bOff[nt] = (uint32_t)((wc * 32 + nt * 16 + bRow) * 128);

    uint32_t ah[2][4][4], bhf[2][2][4];

#define LOAD_FRAGS(buf, sbase, ks_) do {                                        \
    uint32_t soA = (uint32_t)(((2 * (ks_) + aCg) ^ aSwz) << 4);                 \
    uint32_t soB = (uint32_t)(((2 * (ks_) + bCg) ^ bSwz) << 4);                 \
    _Pragma("unroll")                                                           \
    for (int mt = 0; mt < 4; mt++) {                                            \
        ldsm_x4(ah[buf][mt][0], ah[buf][mt][1], ah[buf][mt][2], ah[buf][mt][3], \
                (sbase) + aOff[mt] + soA);                                      \
    }                                                                           \
    _Pragma("unroll")                                                           \
    for (int nt = 0; nt < 2; nt++) {                                            \
        ldsm_x4(bhf[buf][nt][0], bhf[buf][nt][1], bhf[buf][nt][2],              \
                bhf[buf][nt][3], (sbase) + 16384u + bOff[nt] + soB);            \
    }                                                                           \
} while (0)

#define COMPUTE(buf) do {                                                       \
    _Pragma("unroll")                                                           \
    for (int mt = 0; mt < 4; mt++)                                              \
        _Pragma("unroll")                                                       \
        for (int nt = 0; nt < 4; nt++) {                                        \
            const uint32_t* bh2 = &bhf[buf][nt >> 1][(nt & 1) * 2];             \
            mma_fp16(acc[mt][nt], ah[buf][mt], bh2);                            \
        }                                                                       \
} while (0)

    // prologue: global iters 0,1 = tile0 k=0,1
    TileC cur = tile_coords(bid);
    const fp16* curB = Bh_ + (size_t)cur.z * zstride;
#pragma unroll
    for (int s = 0; s < 2; s++) {
        uint32_t st = stage0 + s * STAGE_BYTES;
        load_tile(st,          Ah,   cur.m0, s * 64, tid);
        load_tile(st + 16384u, curB, cur.n0, s * 64, tid);
        asm volatile("cp.async.commit_group;" ::: "memory");
    }

    int it = 0;                // continuous global iteration
    bool first = true;
    for (int j = 0; j < T; j++) {
        TileC nxt;
        const fp16* nxtB = nullptr;
        bool have_nxt = (j + 1 < T);
        if (have_nxt) {
            nxt  = tile_coords(bid + (j + 1) * NPERS);
            nxtB = Bh_ + (size_t)nxt.z * zstride;
        }

        float acc[4][4][4];
#pragma unroll
        for (int a = 0; a < 4; a++)
#pragma unroll
            for (int b = 0; b < 4; b++)
#pragma unroll
                for (int c = 0; c < 4; c++) acc[a][b][c] = 0.f;

        for (int k = 0; k < 16; k++, it++) {
            uint32_t sbase = stage0 + (uint32_t)(it % 3) * STAGE_BYTES;
            bool last_it = (j == T - 1) && (k == 15);

            // ALL outstanding copies complete for every thread BEFORE the
            // barrier -> any smem read below is race-free.
            asm volatile("cp.async.wait_group 0;" ::: "memory");
            __syncthreads();   // also: slot (it-1)%3 free for reuse

            // issue loads for global iter it+2 into slot (it+2)%3 == (it-1)%3
            uint32_t lbase = stage0 + (uint32_t)((it + 2) % 3) * STAGE_BYTES;
            if (k < 14) {
                load_tile(lbase,          Ah,   cur.m0, (k + 2) * 64, tid);
                load_tile(lbase + 16384u, curB, cur.n0, (k + 2) * 64, tid);
                asm volatile("cp.async.commit_group;" ::: "memory");
            } else if (have_nxt) {
                load_tile(lbase,          Ah,   nxt.m0, (k - 14) * 64, tid);
                load_tile(lbase + 16384u, nxtB, nxt.n0, (k - 14) * 64, tid);
                asm volatile("cp.async.commit_group;" ::: "memory");
            }

            if (first) { LOAD_FRAGS(0, sbase, 0); first = false; }

#pragma unroll
            for (int ks = 0; ks < 4; ks++) {
                int cb = ks & 1;
                if (ks < 3) {
                    LOAD_FRAGS((cb ^ 1), sbase, (ks + 1));
                } else if (!last_it) {
                    // prefetch next stage's ks=0 frags (slot (it+1)%3 —
                    // complete and block-visible since before the barrier)
                    uint32_t nbase = stage0 + (uint32_t)((it + 1) % 3) * STAGE_BYTES;
                    LOAD_FRAGS((cb ^ 1), nbase, 0);
                }
                COMPUTE(cb);
            }
        }

        // epilogue (registers -> gmem only; overlaps in-flight cp.async)
        OutT* C = (cur.z == 0) ? C0 : ((cur.z == 1) ? C1 : C2);
        const int mode = ACT ? cur.z : 2;
        const int g4 = lid >> 2;
        const int t4 = lid & 3;
#pragma unroll
        for (int mt = 0; mt < 4; mt++) {
            int row = cur.m0 + wr * 64 + mt * 16 + g4;
#pragma unroll
            for (int nt = 0; nt < 4; nt++) {
                int col = cur.n0 + wc * 32 + nt * 8 + t4 * 2;
                float v0 = ep_xform(acc[mt][nt][0], mode);
                float v1 = ep_xform(acc[mt][nt][1], mode);
                float v2 = ep_xform(acc[mt][nt][2], mode);
                float v3 = ep_xform(acc[mt][nt][3], mode);
                if constexpr (sizeof(OutT) == 2) {
                    *(__half2*)((fp16*)C + (size_t)row * Hx + col)       = __floats2half2_rn(v0, v1);
                    *(__half2*)((fp16*)C + (size_t)(row + 8) * Hx + col) = __floats2half2_rn(v2, v3);
                } else {
                    *(float2*)((float*)C + (size_t)row * Hx + col)       = make_float2(v0, v1);
                    *(float2*)((float*)C + (size_t)(row + 8) * Hx + col) = make_float2(v2, v3);
                }
            }
        }

        cur = nxt;
        curB = nxtB;
    }
}

// ---------------- fused fp32 -> fp16 conversions, x4 vectorized ------------
#define NEc (Mx * Hx)
#define NWc (Hx * Hx)
__global__ void k_cvt_all(const float* __restrict__ x,  const float* __restrict__ Wi,
                          const float* __restrict__ Wf, const float* __restrict__ Wg,
                          const float* __restrict__ Wo) {
    int i = blockIdx.x * blockDim.x + threadIdx.x;      // over (NE + 4NW)/4
    const float* s;
    fp16* d;
    int o;
    if (i < NEc / 4) {
        s = x; d = g_Xh; o = i;
    } else {
        int j = i - NEc / 4;
        int y = j >> 18;                 // j / (NWc/4)
        o = j & (NWc / 4 - 1);
        s = (y == 0) ? Wi : (y == 1) ? Wf : (y == 2) ? Wg : Wo;
        d = (y < 3) ? (g_Wh + (size_t)y * NWc) : g_Woh;
    }
    float4 v = ((const float4*)s)[o];
    __half2 h0 = __floats2half2_rn(v.x, v.y);
    __half2 h1 = __floats2half2_rn(v.z, v.w);
    ((uint2*)d)[o] = make_uint2(h2_bits(h0), h2_bits(h1));
}

// pass 1: chunk-local scan, 2 h-channels per thread (half2 path).
// Summaries written time-major [b][c][h] (coalesced float2 stores).
__global__ void k_scan1() {
    int tid = blockIdx.x * blockDim.x + threadIdx.x;   // B*NCH*H/2 = 131072
    int h2 = tid & 511;          // h-pair
    int bc = tid >> 9;           // b*NCH + c
    size_t base2 = ((size_t)((bc >> 6) * Sx + (bc & (NCH - 1)) * CH)) * (Hx / 2) + h2;
    const __half2* Yf2 = (const __half2*)g_Yf;
    const __half2* Yi2 = (const __half2*)g_Yi;
    float p0 = 1.f, hl0 = 0.f, p1 = 1.f, hl1 = 0.f;
#pragma unroll 4
    for (int t = 0; t < CH; t++) {
        size_t idx = base2 + (size_t)t * (Hx / 2);
        float2 f2 = __half22float2(Yf2[idx]);
        float2 i2 = __half22float2(Yi2[idx]);
        hl0 = f2.x * hl0 + i2.x * (1.f - f2.x);
        p0  = p0 * f2.x;
        hl1 = f2.y * hl1 + i2.y * (1.f - f2.y);
        p1  = p1 * f2.y;
        __half2 ph0 = __floats2half2_rn(p0, hl0);
        __half2 ph1 = __floats2half2_rn(p1, hl1);
        ((uint2*)g_PH)[idx] = make_uint2(h2_bits(ph0), h2_bits(ph1));
    }
    int sidx = (bc << 10) + 2 * h2;
    *(float2*)(g_P + sidx) = make_float2(p0, p1);
    *(float2*)(g_E + sidx) = make_float2(hl0, hl1);
}

// pass 2: smem-staged block scan across chunks.
// 64 blocks x 256 threads; each block owns 64 consecutive channels (same b).
// Phase 1: coalesced load of all 64 chunks x 64 channels into smem.
// Phase 2: 64 threads run the 64-step serial affine scan in smem (exclusive).
// Phase 3: coalesced store of carries to g_Cr.
#define SC2_CH 64
__global__ void k_scan2() {
    __shared__ float sP[NCH][SC2_CH];   // 16 KB
    __shared__ float sE[NCH][SC2_CH];   // 16 KB
    int t   = threadIdx.x;              // 256
    int ch0 = blockIdx.x * SC2_CH;      // global channel base (b*Hx + h)
    int b   = ch0 >> 10;
    int hb  = ch0 & (Hx - 1);
    int hh  = t & 63;
    int cq  = t >> 6;                   // 0..3

#pragma unroll
    for (int r = 0; r < 16; r++) {
        int c = r * 4 + cq;
        int gidx = ((b * NCH + c) << 10) + hb + hh;
        sP[c][hh] = g_P[gidx];
        sE[c][hh] = g_E[gidx];
    }
    __syncthreads();

    if (t < SC2_CH) {
        float carry = 0.f;
#pragma unroll 8
        for (int c = 0; c < NCH; c++) {
            float p = sP[c][t], e = sE[c][t];
            sP[c][t] = carry;               // exclusive carry into chunk c
            carry = p * carry + e;
        }
    }
    __syncthreads();

#pragma unroll
    for (int r = 0; r < 16; r++) {
        int c = r * 4 + cq;
        g_Cr[((b * NCH + c) << 10) + hb + hh] = sP[c][hh];
    }
}

// pass 3: h = h_local + cumprod*carry; gh = g*h; 2 channels per thread
__global__ void k_scan3() {
    int i = blockIdx.x * blockDim.x + threadIdx.x;     // NE/2
    int h2 = i & 511;
    int s = (i >> 9) & (Sx - 1);
    int b = i >> 20;
    int c = s >> 5;                 // CH = 32
    float2 carry = *(float2*)(g_Cr + ((b * NCH + c) << 10) + 2 * h2);
    uint2 phu = ((const uint2*)g_PH)[i];
    __half2 ph0 = *(__half2*)&phu.x;
    __half2 ph1 = *(__half2*)&phu.y;
    float hv0 = __high2float(ph0) + __low2float(ph0) * carry.x;
    float hv1 = __high2float(ph1) + __low2float(ph1) * carry.y;
    float2 g2 = __half22float2(((const __half2*)g_Yg)[i]);
    ((__half2*)g_GH)[i] = __floats2half2_rn(g2.x * hv0, g2.y * hv1);
}

// ---------------- launch ----------------
extern "C" void kernel_launch(void* const* d_in, const int* in_sizes, int n_in,
                              void* d_out, int out_size) {
    const float* x  = (const float*)d_in[0];
    const float* Wi = (const float*)d_in[1];
    const float* Wf = (const float*)d_in[2];
    const float* Wg = (const float*)d_in[3];
    const float* Wo = (const float*)d_in[4];
    float* out = (float*)d_out;

    cudaFuncSetAttribute((const void*)k_gemm_p<fp16, true>,
                         cudaFuncAttributeMaxDynamicSharedMemorySize, GEMM_SMEM);
    cudaFuncSetAttribute((const void*)k_gemm_p<float, false>,
                         cudaFuncAttributeMaxDynamicSharedMemorySize, GEMM_SMEM);

    fp16 *Xh, *Wh, *Woh, *GH, *Yi, *Yf, *Yg;
    cudaGetSymbolAddress((void**)&Xh,  g_Xh);
    cudaGetSymbolAddress((void**)&Wh,  g_Wh);
    cudaGetSymbolAddress((void**)&Woh, g_Woh);
    cudaGetSymbolAddress((void**)&GH,  g_GH);
    cudaGetSymbolAddress((void**)&Yi,  g_Yi);
    cudaGetSymbolAddress((void**)&Yf,  g_Yf);
    cudaGetSymbolAddress((void**)&Yg,  g_Yg);

    const int NE = Mx * Hx;     // 8388608
    const int NW = Hx * Hx;     // 1048576

    // conversions (x4 vectorized)
    k_cvt_all<<<(NE / 4 + NW) / 256, 256>>>(x, Wi, Wf, Wg, Wo);

    // GEMM1 (persistent): Yi = silu(x@Wi^T), Yf = sigmoid(x@Wf^T), Yg = x@Wg^T
    k_gemm_p<fp16, true><<<NPERS, GTHREADS, GEMM_SMEM>>>(Xh, Wh, Yi, Yf, Yg, NW, 1536);

    // chunked linear recurrence
    k_scan1<<<(Bx * NCH * Hx / 2) / 256, 256>>>();
    k_scan2<<<(Bx * Hx) / SC2_CH, 256>>>();
    k_scan3<<<(NE / 2) / 256, 256>>>();

    // GEMM2 (persistent): out = (g*h) @ Wo^T
    k_gemm_p<float, false><<<NPERS, GTHREADS, GEMM_SMEM>>>(GH, Woh, out, out, out, 0, 512);
}